// round 2
// baseline (speedup 1.0000x reference)
#include <cuda_runtime.h>

#define NN 50000
#define NE 800000

// ---------------- device scratch (static allocs are allowed) ----------------
__device__ __align__(16) float g_WPQ[128 * 256];       // fused weights: [k][0:128]=Wp, [128:256]=Wq
__device__ __align__(16) float g_BPQ[256];              // fused biases
__device__ __align__(16) float g_PQ[(size_t)NN * 256];  // per-node [P | Q], bias folded in
__device__ int   g_cnt[NN];
__device__ int   g_cur[NN];
__device__ int   g_esrc[NE];                // src per dst-sorted edge
__device__ int   g_edst[NE];                // dst per dst-sorted edge

// ---------------- trivial init kernels ----------------
__global__ void k_zero_out(float4* out, int n4) {
    int i = blockIdx.x * blockDim.x + threadIdx.x;
    if (i < n4) out[i] = make_float4(0.f, 0.f, 0.f, 0.f);
}

__global__ void k_zero_cnt() {
    int i = blockIdx.x * blockDim.x + threadIdx.x;
    if (i < NN) g_cnt[i] = 0;
}

// ---------------- weight fusion: Wp = W1@(W2a-W2b), Wq = W1@W2b ----------------
// grid 128 (row of W1), 256 threads (output column of WPQ)
__global__ void k_prep_w(const float* __restrict__ W1, const float* __restrict__ b1,
                         const float* __restrict__ W2, const float* __restrict__ b2) {
    __shared__ float w1row[128];
    int i = blockIdx.x;
    if (threadIdx.x < 128) w1row[threadIdx.x] = W1[i * 128 + threadIdx.x];
    __syncthreads();

    int j = threadIdx.x;
    float acc = 0.f;
    if (j < 128) {
        for (int k = 0; k < 128; k++)
            acc += w1row[k] * (W2[k * 128 + j] - W2[(k + 128) * 128 + j]);
    } else {
        int jj = j - 128;
        for (int k = 0; k < 128; k++)
            acc += w1row[k] * W2[(k + 128) * 128 + jj];
    }
    g_WPQ[i * 256 + j] = acc;

    if (i == 0) {
        float b = 0.f;
        if (j < 128) {
            for (int k = 0; k < 128; k++)
                b += b1[k] * (W2[k * 128 + j] - W2[(k + 128) * 128 + j]);
            b += b2[j];
        } else {
            int jj = j - 128;
            for (int k = 0; k < 128; k++)
                b += b1[k] * W2[(k + 128) * 128 + jj];
        }
        g_BPQ[j] = b;
    }
}

// ---------------- node GEMM: PQ[n, 0:256] = x[n] @ WPQ + BPQ ----------------
// tile M=64, N=256, K=128 (chunks of 32); 256 threads, 8x8 per thread
__global__ void __launch_bounds__(256) k_node_gemm(const float* __restrict__ x) {
    __shared__ float xsT[32 * 64];   // [k][r]
    __shared__ float ws[32 * 256];   // [k][c]
    int tid = threadIdx.x;
    int row0 = blockIdx.x * 64;
    int tm = tid >> 5;               // 0..7  (rows tm*8 .. +7)
    int tc = tid & 31;               // 0..31
    int clo = tc * 4;                // cols clo..clo+3
    int chi = 128 + tc * 4;          // cols chi..chi+3

    float acc[8][8];
    {
        float4 blo = *(const float4*)&g_BPQ[clo];
        float4 bhi = *(const float4*)&g_BPQ[chi];
#pragma unroll
        for (int i = 0; i < 8; i++) {
            acc[i][0] = blo.x; acc[i][1] = blo.y; acc[i][2] = blo.z; acc[i][3] = blo.w;
            acc[i][4] = bhi.x; acc[i][5] = bhi.y; acc[i][6] = bhi.z; acc[i][7] = bhi.w;
        }
    }

    for (int kc = 0; kc < 4; kc++) {
        // x chunk, transposed [k][r]
#pragma unroll
        for (int i = 0; i < 8; i++) {
            int lin = tid + i * 256;        // 0..2047
            int r = lin & 63;
            int k = lin >> 6;               // 0..31
            int row = row0 + r;
            float v = 0.f;
            if (row < NN) v = x[row * 128 + kc * 32 + k];
            xsT[k * 64 + r] = v;
        }
        // W chunk [k][c]
#pragma unroll
        for (int i = 0; i < 32; i++) {
            int lin = tid + i * 256;        // 0..8191
            ws[lin] = g_WPQ[(kc * 32 + (lin >> 8)) * 256 + (lin & 255)];
        }
        __syncthreads();

#pragma unroll
        for (int k = 0; k < 32; k++) {
            float4 a0 = *(float4*)&xsT[k * 64 + tm * 8];
            float4 a1 = *(float4*)&xsT[k * 64 + tm * 8 + 4];
            float4 w0 = *(float4*)&ws[k * 256 + clo];
            float4 w1 = *(float4*)&ws[k * 256 + chi];
            float a[8] = {a0.x, a0.y, a0.z, a0.w, a1.x, a1.y, a1.z, a1.w};
            float w[8] = {w0.x, w0.y, w0.z, w0.w, w1.x, w1.y, w1.z, w1.w};
#pragma unroll
            for (int i = 0; i < 8; i++)
#pragma unroll
                for (int j = 0; j < 8; j++)
                    acc[i][j] = fmaf(a[i], w[j], acc[i][j]);
        }
        __syncthreads();
    }

#pragma unroll
    for (int i = 0; i < 8; i++) {
        int row = row0 + tm * 8 + i;
        if (row < NN) {
            float4 vlo = make_float4(acc[i][0], acc[i][1], acc[i][2], acc[i][3]);
            float4 vhi = make_float4(acc[i][4], acc[i][5], acc[i][6], acc[i][7]);
            *(float4*)&g_PQ[(size_t)row * 256 + clo] = vlo;
            *(float4*)&g_PQ[(size_t)row * 256 + chi] = vhi;
        }
    }
}

// ---------------- CSR build: histogram / scan / scatter ----------------
// edge_index arrives as int32: ei[0:NE]=src, ei[NE:2NE]=dst
__global__ void k_hist(const int* __restrict__ ei) {
    int e = blockIdx.x * blockDim.x + threadIdx.x;
    if (e < NE) atomicAdd(&g_cnt[ei[NE + e]], 1);
}

__global__ void k_scan() {
    __shared__ int s[1024];
    const int CH = 49;                       // 1024*49 >= 50000
    int t = threadIdx.x;
    int start = t * CH;
    int sum = 0;
    for (int i = 0; i < CH; i++) {
        int idx = start + i;
        if (idx < NN) sum += g_cnt[idx];
    }
    s[t] = sum;
    __syncthreads();
    for (int d = 1; d < 1024; d <<= 1) {
        int v = (t >= d) ? s[t - d] : 0;
        __syncthreads();
        s[t] += v;
        __syncthreads();
    }
    int run = s[t] - sum;                    // exclusive prefix of this chunk
    for (int i = 0; i < CH; i++) {
        int idx = start + i;
        if (idx < NN) {
            g_cur[idx] = run;
            run += g_cnt[idx];
        }
    }
}

__global__ void k_scatter(const int* __restrict__ ei) {
    int e = blockIdx.x * blockDim.x + threadIdx.x;
    if (e < NE) {
        int d  = ei[NE + e];
        int sr = ei[e];
        int pos = atomicAdd(&g_cur[d], 1);
        g_esrc[pos] = sr;
        g_edst[pos] = d;
    }
}

// ---------------- fused edge GEMM + segmented scatter-max ----------------
// 64 dst-sorted edges per block; m1 = relu(P[dst]+Q[src]) built in smem (transposed),
// m2 = relu(m1 @ W3 + b3) via 8x8 register tiling, run-merged max -> atomicMax.
__global__ void __launch_bounds__(128) k_edge(const float* __restrict__ W3,
                                              const float* __restrict__ b3,
                                              float* __restrict__ out) {
    extern __shared__ float sm[];
    float* m1T  = sm;                        // [128 k][64 r]
    float* w3s  = sm + 128 * 64;             // [128 k][128 c]
    int*   sdst = (int*)(w3s + 128 * 128);   // [64]

    int tid = threadIdx.x;
    int base = blockIdx.x * 64;

    // stage W3 (coalesced float4)
    {
        const float4* g = (const float4*)W3;
        float4* s = (float4*)w3s;
#pragma unroll
        for (int i = 0; i < 32; i++) s[tid + i * 128] = g[tid + i * 128];
    }
    if (tid < 64) sdst[tid] = g_edst[base + tid];

    // build m1T: 2 threads per edge row, 64 k's each
    {
        int r = tid & 63;
        int h = tid >> 6;
        int dst = g_edst[base + r];
        int src = g_esrc[base + r];
        const float4* pv = (const float4*)(g_PQ + (size_t)dst * 256 + h * 64);
        const float4* qv = (const float4*)(g_PQ + (size_t)src * 256 + 128 + h * 64);
#pragma unroll
        for (int c = 0; c < 16; c++) {
            float4 a = pv[c];
            float4 b = qv[c];
            int k = h * 64 + c * 4;
            m1T[(k + 0) * 64 + r] = fmaxf(a.x + b.x, 0.f);
            m1T[(k + 1) * 64 + r] = fmaxf(a.y + b.y, 0.f);
            m1T[(k + 2) * 64 + r] = fmaxf(a.z + b.z, 0.f);
            m1T[(k + 3) * 64 + r] = fmaxf(a.w + b.w, 0.f);
        }
    }
    __syncthreads();

    int tm = tid >> 4;       // 0..7  rows tm*8..+7
    int tc = tid & 15;       // 0..15 cols tc*8..+7
    float acc[8][8];
    {
        float4 bl = *(const float4*)&b3[tc * 8];
        float4 bh = *(const float4*)&b3[tc * 8 + 4];
#pragma unroll
        for (int i = 0; i < 8; i++) {
            acc[i][0] = bl.x; acc[i][1] = bl.y; acc[i][2] = bl.z; acc[i][3] = bl.w;
            acc[i][4] = bh.x; acc[i][5] = bh.y; acc[i][6] = bh.z; acc[i][7] = bh.w;
        }
    }

#pragma unroll 4
    for (int k = 0; k < 128; k++) {
        float4 a0 = *(float4*)&m1T[k * 64 + tm * 8];
        float4 a1 = *(float4*)&m1T[k * 64 + tm * 8 + 4];
        float4 w0 = *(float4*)&w3s[k * 128 + tc * 8];
        float4 w1 = *(float4*)&w3s[k * 128 + tc * 8 + 4];
        float a[8] = {a0.x, a0.y, a0.z, a0.w, a1.x, a1.y, a1.z, a1.w};
        float w[8] = {w0.x, w0.y, w0.z, w0.w, w1.x, w1.y, w1.z, w1.w};
#pragma unroll
        for (int i = 0; i < 8; i++)
#pragma unroll
            for (int j = 0; j < 8; j++)
                acc[i][j] = fmaf(a[i], w[j], acc[i][j]);
    }

    // epilogue: relu + run-merge equal-dst rows, then atomicMax (int trick, vals >= 0)
    int rbase = tm * 8;
    float mx[8];
    int curd = sdst[rbase];
#pragma unroll
    for (int j = 0; j < 8; j++) mx[j] = fmaxf(acc[0][j], 0.f);
#pragma unroll
    for (int i = 1; i < 8; i++) {
        int d = sdst[rbase + i];
        if (d != curd) {
            int* op = (int*)out + (size_t)curd * 128 + tc * 8;
#pragma unroll
            for (int j = 0; j < 8; j++)
                if (mx[j] > 0.f) atomicMax(&op[j], __float_as_int(mx[j]));
            curd = d;
#pragma unroll
            for (int j = 0; j < 8; j++) mx[j] = fmaxf(acc[i][j], 0.f);
        } else {
#pragma unroll
            for (int j = 0; j < 8; j++) mx[j] = fmaxf(mx[j], acc[i][j]);
        }
    }
    {
        int* op = (int*)out + (size_t)curd * 128 + tc * 8;
#pragma unroll
        for (int j = 0; j < 8; j++)
            if (mx[j] > 0.f) atomicMax(&op[j], __float_as_int(mx[j]));
    }
}

// ---------------- launch ----------------
extern "C" void kernel_launch(void* const* d_in, const int* in_sizes, int n_in,
                              void* d_out, int out_size) {
    const float* x  = (const float*)d_in[0];
    const int*   ei = (const int*)d_in[1];       // int32 edge_index [2, NE]
    const float* W1 = (const float*)d_in[2];
    const float* b1 = (const float*)d_in[3];
    const float* W2 = (const float*)d_in[4];
    const float* b2 = (const float*)d_in[5];
    const float* W3 = (const float*)d_in[6];
    const float* b3 = (const float*)d_in[7];
    float* out = (float*)d_out;

    const int EDGE_SMEM = (128 * 64 + 128 * 128) * 4 + 64 * 4;  // 98560 B
    cudaFuncSetAttribute(k_edge, cudaFuncAttributeMaxDynamicSharedMemorySize, EDGE_SMEM);

    k_zero_out<<<(NN * 128 / 4 + 255) / 256, 256>>>((float4*)out, NN * 128 / 4);
    k_zero_cnt<<<(NN + 255) / 256, 256>>>();
    k_prep_w<<<128, 256>>>(W1, b1, W2, b2);
    k_node_gemm<<<(NN + 63) / 64, 256>>>(x);
    k_hist<<<NE / 256, 256>>>(ei);
    k_scan<<<1, 1024>>>();
    k_scatter<<<NE / 256, 256>>>(ei);
    k_edge<<<NE / 64, 128, EDGE_SMEM>>>(W3, b3, out);
}

// round 4
// speedup vs baseline: 1.9505x; 1.9505x over previous
#include <cuda_runtime.h>
#include <cuda_fp16.h>
#include <cstdint>

#define NN 50000
#define NE 800000
#define NT (NE / 128)

// ---------------- device scratch ----------------
__device__ __align__(16) float g_WPQ[128 * 256];
__device__ __align__(16) float g_BPQ[256];
__device__ __align__(16) float g_PQ[(size_t)NN * 256];
__device__ int   g_cnt[NN];
__device__ int   g_cur[NN];
__device__ int   g_esrc[NE];
__device__ int   g_edst[NE];

// ---------------- helpers ----------------
__device__ __forceinline__ uint32_t smem_u32(const void* p) {
    uint32_t a;
    asm("{ .reg .u64 t; cvta.to.shared.u64 t, %1; cvt.u32.u64 %0, t; }" : "=r"(a) : "l"(p));
    return a;
}
__device__ __forceinline__ void ldsm_x4(uint32_t* r, uint32_t addr) {
    asm volatile("ldmatrix.sync.aligned.m8n8.x4.shared.b16 {%0,%1,%2,%3}, [%4];"
                 : "=r"(r[0]), "=r"(r[1]), "=r"(r[2]), "=r"(r[3]) : "r"(addr));
}
__device__ __forceinline__ void ldsm_x2t(uint32_t* r, uint32_t addr) {
    asm volatile("ldmatrix.sync.aligned.m8n8.x2.trans.shared.b16 {%0,%1}, [%2];"
                 : "=r"(r[0]), "=r"(r[1]) : "r"(addr));
}
__device__ __forceinline__ void mma16816(float* d, const uint32_t* a, const uint32_t* b) {
    asm volatile(
        "mma.sync.aligned.m16n8k16.row.col.f32.f16.f16.f32 "
        "{%0,%1,%2,%3}, {%4,%5,%6,%7}, {%8,%9}, {%0,%1,%2,%3};"
        : "+f"(d[0]), "+f"(d[1]), "+f"(d[2]), "+f"(d[3])
        : "r"(a[0]), "r"(a[1]), "r"(a[2]), "r"(a[3]), "r"(b[0]), "r"(b[1]));
}

// ---------------- trivial init kernels ----------------
__global__ void k_zero_out(float4* out, int n4) {
    int i = blockIdx.x * blockDim.x + threadIdx.x;
    if (i < n4) out[i] = make_float4(0.f, 0.f, 0.f, 0.f);
}
__global__ void k_zero_cnt() {
    int i = blockIdx.x * blockDim.x + threadIdx.x;
    if (i < NN) g_cnt[i] = 0;
}

// ---------------- weight fusion ----------------
__global__ void k_prep_w(const float* __restrict__ W1, const float* __restrict__ b1,
                         const float* __restrict__ W2, const float* __restrict__ b2) {
    __shared__ float w1row[128];
    int i = blockIdx.x;
    if (threadIdx.x < 128) w1row[threadIdx.x] = W1[i * 128 + threadIdx.x];
    __syncthreads();
    int j = threadIdx.x;
    float acc = 0.f;
    if (j < 128) {
        for (int k = 0; k < 128; k++)
            acc += w1row[k] * (W2[k * 128 + j] - W2[(k + 128) * 128 + j]);
    } else {
        int jj = j - 128;
        for (int k = 0; k < 128; k++)
            acc += w1row[k] * W2[(k + 128) * 128 + jj];
    }
    g_WPQ[i * 256 + j] = acc;
    if (i == 0) {
        float b = 0.f;
        if (j < 128) {
            for (int k = 0; k < 128; k++)
                b += b1[k] * (W2[k * 128 + j] - W2[(k + 128) * 128 + j]);
            b += b2[j];
        } else {
            int jj = j - 128;
            for (int k = 0; k < 128; k++)
                b += b1[k] * W2[(k + 128) * 128 + jj];
        }
        g_BPQ[j] = b;
    }
}

// ---------------- node GEMM (fp32, near-roofline) ----------------
__global__ void __launch_bounds__(256) k_node_gemm(const float* __restrict__ x) {
    __shared__ float xsT[32 * 64];
    __shared__ float ws[32 * 256];
    int tid = threadIdx.x;
    int row0 = blockIdx.x * 64;
    int tm = tid >> 5;
    int tc = tid & 31;
    int clo = tc * 4;
    int chi = 128 + tc * 4;

    float acc[8][8];
    {
        float4 blo = *(const float4*)&g_BPQ[clo];
        float4 bhi = *(const float4*)&g_BPQ[chi];
#pragma unroll
        for (int i = 0; i < 8; i++) {
            acc[i][0] = blo.x; acc[i][1] = blo.y; acc[i][2] = blo.z; acc[i][3] = blo.w;
            acc[i][4] = bhi.x; acc[i][5] = bhi.y; acc[i][6] = bhi.z; acc[i][7] = bhi.w;
        }
    }
    for (int kc = 0; kc < 4; kc++) {
#pragma unroll
        for (int i = 0; i < 8; i++) {
            int lin = tid + i * 256;
            int r = lin & 63;
            int k = lin >> 6;
            int row = row0 + r;
            float v = 0.f;
            if (row < NN) v = x[row * 128 + kc * 32 + k];
            xsT[k * 64 + r] = v;
        }
#pragma unroll
        for (int i = 0; i < 32; i++) {
            int lin = tid + i * 256;
            ws[lin] = g_WPQ[(kc * 32 + (lin >> 8)) * 256 + (lin & 255)];
        }
        __syncthreads();
#pragma unroll
        for (int k = 0; k < 32; k++) {
            float4 a0 = *(float4*)&xsT[k * 64 + tm * 8];
            float4 a1 = *(float4*)&xsT[k * 64 + tm * 8 + 4];
            float4 w0 = *(float4*)&ws[k * 256 + clo];
            float4 w1 = *(float4*)&ws[k * 256 + chi];
            float a[8] = {a0.x, a0.y, a0.z, a0.w, a1.x, a1.y, a1.z, a1.w};
            float w[8] = {w0.x, w0.y, w0.z, w0.w, w1.x, w1.y, w1.z, w1.w};
#pragma unroll
            for (int i = 0; i < 8; i++)
#pragma unroll
                for (int j = 0; j < 8; j++)
                    acc[i][j] = fmaf(a[i], w[j], acc[i][j]);
        }
        __syncthreads();
    }
#pragma unroll
    for (int i = 0; i < 8; i++) {
        int row = row0 + tm * 8 + i;
        if (row < NN) {
            *(float4*)&g_PQ[(size_t)row * 256 + clo] =
                make_float4(acc[i][0], acc[i][1], acc[i][2], acc[i][3]);
            *(float4*)&g_PQ[(size_t)row * 256 + chi] =
                make_float4(acc[i][4], acc[i][5], acc[i][6], acc[i][7]);
        }
    }
}

// ---------------- CSR build ----------------
__global__ void k_hist(const int* __restrict__ ei) {
    int e = blockIdx.x * blockDim.x + threadIdx.x;
    if (e < NE) atomicAdd(&g_cnt[ei[NE + e]], 1);
}
__global__ void k_scan() {
    __shared__ int s[1024];
    const int CH = 49;
    int t = threadIdx.x;
    int start = t * CH;
    int sum = 0;
    for (int i = 0; i < CH; i++) {
        int idx = start + i;
        if (idx < NN) sum += g_cnt[idx];
    }
    s[t] = sum;
    __syncthreads();
    for (int d = 1; d < 1024; d <<= 1) {
        int v = (t >= d) ? s[t - d] : 0;
        __syncthreads();
        s[t] += v;
        __syncthreads();
    }
    int run = s[t] - sum;
    for (int i = 0; i < CH; i++) {
        int idx = start + i;
        if (idx < NN) {
            g_cur[idx] = run;
            run += g_cnt[idx];
        }
    }
}
__global__ void k_scatter(const int* __restrict__ ei) {
    int e = blockIdx.x * blockDim.x + threadIdx.x;
    if (e < NE) {
        int d = ei[NE + e];
        int sr = ei[e];
        int pos = atomicAdd(&g_cur[d], 1);
        g_esrc[pos] = sr;
        g_edst[pos] = d;
    }
}

// ---------------- HMMA edge kernel ----------------
// smem layout (bytes):
//   [0, 32768)      Ah: fp16 m1 hi, [128 r][128 k], 256B rows, chunk-XOR swizzle
//   [32768, 65536)  Al: fp16 m1 lo
//   [65536, 98304)  Bh: fp16 W3,    [128 k][128 n], 256B rows, chunk-XOR swizzle
//   [98304, 98816)  b3s (128 f32)
//   [98816, 99328)  sdst (128 int)
//   accf overlay:   [0, 67584) f32 [128 r][132 c]  (after all mma done)
#define oAh 0u
#define oAl 32768u
#define oBh 65536u
#define oB3 98304u
#define oSD 98816u
#define EDGE_SMEM 99328

__global__ void __launch_bounds__(256, 2) k_edge_mma(const float* __restrict__ W3,
                                                     const float* __restrict__ b3,
                                                     float* __restrict__ out) {
    extern __shared__ char smb[];
    uint32_t sb = smem_u32(smb);
    int tid = threadIdx.x, lane = tid & 31, wid = tid >> 5;

    // stage b3
    if (tid < 128) ((float*)(smb + oB3))[tid] = b3[tid];

    // stage Bh = fp16(W3), [k][n] with chunk swizzle cj' = (n/8) ^ (k&7)
#pragma unroll
    for (int q = tid; q < 2048; q += 256) {
        int k = q >> 4, cj = q & 15;
        const float* wp = W3 + k * 128 + cj * 8;
        float4 f0 = *(const float4*)wp;
        float4 f1 = *(const float4*)(wp + 4);
        __half2 h0 = __floats2half2_rn(f0.x, f0.y);
        __half2 h1 = __floats2half2_rn(f0.z, f0.w);
        __half2 h2 = __floats2half2_rn(f1.x, f1.y);
        __half2 h3 = __floats2half2_rn(f1.z, f1.w);
        uint4 pk = make_uint4(*(uint32_t*)&h0, *(uint32_t*)&h1, *(uint32_t*)&h2, *(uint32_t*)&h3);
        *(uint4*)(smb + oBh + (uint32_t)(k * 256) + (uint32_t)(((cj ^ (k & 7))) << 4)) = pk;
    }

    // build A = m1 = relu(P[dst] + Q[src]) split to fp16 hi+lo
    {
        int r = tid & 127, hh = tid >> 7;
        int e = blockIdx.x * 128 + r;
        int dst = g_edst[e];
        int src = g_esrc[e];
        if (hh == 0) ((int*)(smb + oSD))[r] = dst;
        const float4* pv = (const float4*)(g_PQ + (size_t)dst * 256) + hh * 16;
        const float4* qv = (const float4*)(g_PQ + (size_t)src * 256 + 128) + hh * 16;
        uint32_t rowbase = (uint32_t)(r * 256);
#pragma unroll
        for (int c = 0; c < 8; c++) {
            float4 a0 = pv[c * 2], b0 = qv[c * 2];
            float4 a1 = pv[c * 2 + 1], b1 = qv[c * 2 + 1];
            float v[8] = {fmaxf(a0.x + b0.x, 0.f), fmaxf(a0.y + b0.y, 0.f),
                          fmaxf(a0.z + b0.z, 0.f), fmaxf(a0.w + b0.w, 0.f),
                          fmaxf(a1.x + b1.x, 0.f), fmaxf(a1.y + b1.y, 0.f),
                          fmaxf(a1.z + b1.z, 0.f), fmaxf(a1.w + b1.w, 0.f)};
            uint32_t hi[4], lo[4];
#pragma unroll
            for (int p = 0; p < 4; p++) {
                __half hx = __float2half_rn(v[p * 2]);
                __half hy = __float2half_rn(v[p * 2 + 1]);
                __half lx = __float2half_rn(v[p * 2] - __half2float(hx));
                __half ly = __float2half_rn(v[p * 2 + 1] - __half2float(hy));
                __half2 hh2 = __halves2half2(hx, hy);
                __half2 ll2 = __halves2half2(lx, ly);
                hi[p] = *(uint32_t*)&hh2;
                lo[p] = *(uint32_t*)&ll2;
            }
            int cj = hh * 8 + c;
            uint32_t off = rowbase + (uint32_t)((cj ^ (r & 7)) << 4);
            *(uint4*)(smb + oAh + off) = make_uint4(hi[0], hi[1], hi[2], hi[3]);
            *(uint4*)(smb + oAl + off) = make_uint4(lo[0], lo[1], lo[2], lo[3]);
        }
    }
    __syncthreads();

    // ---- MMA: warp grid 4(M) x 2(N); warp tile 32x64 ----
    int m0 = (wid & 3) * 32;
    int n0 = (wid >> 2) * 64;
    float acc[2][8][4];
#pragma unroll
    for (int a = 0; a < 2; a++)
#pragma unroll
        for (int b = 0; b < 8; b++)
#pragma unroll
            for (int c = 0; c < 4; c++) acc[a][b][c] = 0.f;

    int arow0 = m0 + (lane & 15);
    int arow1 = arow0 + 16;
    int bk_lane = lane & 15;

#pragma unroll
    for (int ks = 0; ks < 8; ks++) {
        int chunk = ks * 2 + (lane >> 4);
        uint32_t ah0[4], ah1[4], al0[4], al1[4];
        uint32_t a0addr = sb + oAh + (uint32_t)(arow0 * 256) + (uint32_t)((chunk ^ (arow0 & 7)) << 4);
        uint32_t a1addr = sb + oAh + (uint32_t)(arow1 * 256) + (uint32_t)((chunk ^ (arow1 & 7)) << 4);
        ldsm_x4(ah0, a0addr);
        ldsm_x4(ah1, a1addr);
        ldsm_x4(al0, a0addr + 32768u);
        ldsm_x4(al1, a1addr + 32768u);

        int bk = ks * 16 + bk_lane;
        uint32_t brow = sb + oBh + (uint32_t)(bk * 256);
        int bsw = bk & 7;
#pragma unroll
        for (int nt = 0; nt < 8; nt++) {
            uint32_t bfr[2];
            ldsm_x2t(bfr, brow + (uint32_t)((((n0 >> 3) + nt) ^ bsw) << 4));
            mma16816(acc[0][nt], ah0, bfr);
            mma16816(acc[1][nt], ah1, bfr);
            mma16816(acc[0][nt], al0, bfr);
            mma16816(acc[1][nt], al1, bfr);
        }
    }
    __syncthreads();

    // ---- dump acc to smem accf [128][132] f32 (overlays A/B) ----
    float* accf = (float*)smb;
    {
        int rr = lane >> 2, cc = 2 * (lane & 3);
#pragma unroll
        for (int mt = 0; mt < 2; mt++)
#pragma unroll
            for (int nt = 0; nt < 8; nt++) {
                int r_ = m0 + mt * 16 + rr;
                int c_ = n0 + nt * 8 + cc;
                *(float2*)&accf[r_ * 132 + c_] = make_float2(acc[mt][nt][0], acc[mt][nt][1]);
                *(float2*)&accf[(r_ + 8) * 132 + c_] = make_float2(acc[mt][nt][2], acc[mt][nt][3]);
            }
    }
    __syncthreads();

    // ---- epilogue: bias + relu + run-merged segmented max + atomicMax ----
    {
        int cg = tid & 31;        // cols cg*4..+3
        int rg = tid >> 5;        // rows rg*16..+15
        const float* b3s = (const float*)(smb + oB3);
        const int* sd = (const int*)(smb + oSD);
        float4 bias = *(const float4*)&b3s[cg * 4];
        int rbase = rg * 16;
        int curd = sd[rbase];
        float4 v = *(float4*)&accf[rbase * 132 + cg * 4];
        float4 mx = make_float4(fmaxf(v.x + bias.x, 0.f), fmaxf(v.y + bias.y, 0.f),
                                fmaxf(v.z + bias.z, 0.f), fmaxf(v.w + bias.w, 0.f));
#pragma unroll
        for (int i = 1; i < 16; i++) {
            int d = sd[rbase + i];
            float4 u = *(float4*)&accf[(rbase + i) * 132 + cg * 4];
            float4 w = make_float4(fmaxf(u.x + bias.x, 0.f), fmaxf(u.y + bias.y, 0.f),
                                   fmaxf(u.z + bias.z, 0.f), fmaxf(u.w + bias.w, 0.f));
            if (d != curd) {
                int* op = (int*)out + (size_t)curd * 128 + cg * 4;
                if (mx.x > 0.f) atomicMax(op + 0, __float_as_int(mx.x));
                if (mx.y > 0.f) atomicMax(op + 1, __float_as_int(mx.y));
                if (mx.z > 0.f) atomicMax(op + 2, __float_as_int(mx.z));
                if (mx.w > 0.f) atomicMax(op + 3, __float_as_int(mx.w));
                curd = d;
                mx = w;
            } else {
                mx.x = fmaxf(mx.x, w.x);
                mx.y = fmaxf(mx.y, w.y);
                mx.z = fmaxf(mx.z, w.z);
                mx.w = fmaxf(mx.w, w.w);
            }
        }
        int* op = (int*)out + (size_t)curd * 128 + cg * 4;
        if (mx.x > 0.f) atomicMax(op + 0, __float_as_int(mx.x));
        if (mx.y > 0.f) atomicMax(op + 1, __float_as_int(mx.y));
        if (mx.z > 0.f) atomicMax(op + 2, __float_as_int(mx.z));
        if (mx.w > 0.f) atomicMax(op + 3, __float_as_int(mx.w));
    }
}

// ---------------- launch ----------------
extern "C" void kernel_launch(void* const* d_in, const int* in_sizes, int n_in,
                              void* d_out, int out_size) {
    const float* x  = (const float*)d_in[0];
    const int*   ei = (const int*)d_in[1];
    const float* W1 = (const float*)d_in[2];
    const float* b1 = (const float*)d_in[3];
    const float* W2 = (const float*)d_in[4];
    const float* b2 = (const float*)d_in[5];
    const float* W3 = (const float*)d_in[6];
    const float* b3 = (const float*)d_in[7];
    float* out = (float*)d_out;

    cudaFuncSetAttribute(k_edge_mma, cudaFuncAttributeMaxDynamicSharedMemorySize, EDGE_SMEM);

    k_zero_out<<<(NN * 128 / 4 + 255) / 256, 256>>>((float4*)out, NN * 128 / 4);
    k_zero_cnt<<<(NN + 255) / 256, 256>>>();
    k_prep_w<<<128, 256>>>(W1, b1, W2, b2);
    k_node_gemm<<<(NN + 63) / 64, 256>>>(x);
    k_hist<<<NE / 256, 256>>>(ei);
    k_scan<<<1, 1024>>>();
    k_scatter<<<NE / 256, 256>>>(ei);
    k_edge_mma<<<NT, 256, EDGE_SMEM>>>(W3, b3, out);
}